// round 6
// baseline (speedup 1.0000x reference)
#include <cuda_runtime.h>
#include <math.h>

typedef unsigned long long ull;

#define FEAT_DIM 360
#define MAXB     32
#define NT       256
#define TILE     32

__device__ float g_feat[MAXB * FEAT_DIM];

// ---------------- packed f32x2 helpers ----------------
__device__ __forceinline__ ull pack2(float lo, float hi) {
    ull r; asm("mov.b64 %0, {%1, %2};" : "=l"(r) : "f"(lo), "f"(hi)); return r;
}
__device__ __forceinline__ ull fma2(ull a, ull b, ull c) {
    ull r; asm("fma.rn.f32x2 %0, %1, %2, %3;" : "=l"(r) : "l"(a), "l"(b), "l"(c)); return r;
}
__device__ __forceinline__ ull mul2(ull a, ull b) {
    ull r; asm("mul.rn.f32x2 %0, %1, %2;" : "=l"(r) : "l"(a), "l"(b)); return r;
}
__device__ __forceinline__ ull add2(ull a, ull b) {
    ull r; asm("add.rn.f32x2 %0, %1, %2;" : "=l"(r) : "l"(a), "l"(b)); return r;
}

#define C06P 0x3F19999A3F19999AULL   // (0.6f, 0.6f)
#define C04P 0x3ECCCCCD3ECCCCCDULL   // (0.4f, 0.4f)
#define ONE2 0x3F8000003F800000ULL   // (1.0f, 1.0f)

// lrelu(v) = 0.6*v + 0.4*|v|  (exact), branch-free packed
__device__ __forceinline__ ull lrelu2(ull v) {
    ull a = v & 0x7FFFFFFF7FFFFFFFULL;
    return fma2(a, (ull)C04P, mul2(v, (ull)C06P));
}

// ---------------- merged preamble: mean(thumb) + GEMV ----------------
#define FT 384
__global__ void feat_kernel(const float* __restrict__ thumb,
                            const float* __restrict__ Wm,
                            const float* __restrict__ bm, int HW) {
    int b = blockIdx.x;
    int tid = threadIdx.x;
    __shared__ float red[FT / 32][3];
    __shared__ float m[3];
    const float4* p = (const float4*)(thumb + (size_t)b * 3 * HW);
    int n4c = HW / 4;
    float s[3];
    #pragma unroll
    for (int c = 0; c < 3; c++) {
        float acc = 0.0f;
        for (int i = tid; i < n4c; i += FT) {
            float4 v = p[c * n4c + i];
            acc += (v.x + v.y) + (v.z + v.w);
        }
        s[c] = acc;
    }
    #pragma unroll
    for (int c = 0; c < 3; c++) {
        float v = s[c];
        #pragma unroll
        for (int o = 16; o > 0; o >>= 1) v += __shfl_down_sync(0xffffffffu, v, o);
        if ((tid & 31) == 0) red[tid >> 5][c] = v;
    }
    __syncthreads();
    if (tid == 0) {
        float inv = 1.0f / (float)HW;
        #pragma unroll
        for (int c = 0; c < 3; c++) {
            float t = 0.0f;
            #pragma unroll
            for (int w = 0; w < FT / 32; w++) t += red[w][c];
            m[c] = t * inv;
        }
    }
    __syncthreads();
    if (tid < FEAT_DIM) {
        g_feat[b * FEAT_DIM + tid] =
            m[0] * Wm[tid] + m[1] * Wm[FEAT_DIM + tid] + m[2] * Wm[2 * FEAT_DIM + tid]
            + bm[tid];
    }
}

// ---------------- one 3x3 conv layer on pixel pairs ----------------
// Weight layout per layer (96 ull): 9 groups g=ic*3+ky at g*10, each
// [ (kx,oc) j=kx*3+oc : 9 ull ] + 1 pad; bias at 90..92. 16B-aligned groups ->
// 4x LDS.128 + 1x LDS.64 per group instead of 9x LDS.64.
template <int S, int D, int SLOTS, bool STORE>
__device__ __forceinline__ void conv3_pairs(const float* __restrict__ src,
                                            float* __restrict__ dst,
                                            const ull* __restrict__ wL,
                                            int tid, ull outReg[][3]) {
    constexpr int PW = D / 2;
    constexpr int NP = D * PW;
    int off[SLOTS], oy[SLOTS], ox[SLOTS];
    #pragma unroll
    for (int k = 0; k < SLOTS; k++) {
        int p = tid + k * NT;
        int y = p / PW, x = (p - y * PW) * 2;
        oy[k] = y; ox[k] = x;
        off[k] = y * S + x;
    }
    ull acc[SLOTS][3];
    #pragma unroll
    for (int oc = 0; oc < 3; oc++) {
        ull bb = wL[90 + oc];
        #pragma unroll
        for (int k = 0; k < SLOTS; k++) acc[k][oc] = bb;
    }
    #pragma unroll
    for (int g = 0; g < 9; g++) {            // g = ic*3 + ky
        const int ic = g / 3, ky = g - ic * 3;
        const ull* wb = wL + g * 10;
        ulonglong2 p01 = *(const ulonglong2*)(wb);
        ulonglong2 p23 = *(const ulonglong2*)(wb + 2);
        ulonglong2 p45 = *(const ulonglong2*)(wb + 4);
        ulonglong2 p67 = *(const ulonglong2*)(wb + 6);
        ull w8 = wb[8];
        #pragma unroll
        for (int k = 0; k < SLOTS; k++) {
            bool active = ((k + 1) * NT <= NP) || (tid + k * NT < NP);
            if (active) {
                const float* s = src + ic * S * S + ky * S + off[k];
                float2 a = *(const float2*)s;
                float2 b = *(const float2*)(s + 2);
                ull v0 = pack2(a.x, a.y);
                ull v1 = pack2(a.y, b.x);
                ull v2 = pack2(b.x, b.y);
                acc[k][0] = fma2(p01.x, v0, acc[k][0]);   // kx0,oc0
                acc[k][1] = fma2(p01.y, v0, acc[k][1]);   // kx0,oc1
                acc[k][2] = fma2(p23.x, v0, acc[k][2]);   // kx0,oc2
                acc[k][0] = fma2(p23.y, v1, acc[k][0]);   // kx1,oc0
                acc[k][1] = fma2(p45.x, v1, acc[k][1]);   // kx1,oc1
                acc[k][2] = fma2(p45.y, v1, acc[k][2]);   // kx1,oc2
                acc[k][0] = fma2(p67.x, v2, acc[k][0]);   // kx2,oc0
                acc[k][1] = fma2(p67.y, v2, acc[k][1]);   // kx2,oc1
                acc[k][2] = fma2(w8,    v2, acc[k][2]);   // kx2,oc2
            }
        }
    }
    #pragma unroll
    for (int k = 0; k < SLOTS; k++) {
        bool active = ((k + 1) * NT <= NP) || (tid + k * NT < NP);
        if (active) {
            #pragma unroll
            for (int oc = 0; oc < 3; oc++) {
                ull r = lrelu2(acc[k][oc]);
                if (STORE) *(ull*)(dst + oc * D * D + oy[k] * D + ox[k]) = r;
                else       outReg[k][oc] = r;
            }
        }
    }
}

// smem partition (ull units): sPack 396 | bufA 2166 | bufB 1944 | bufC 1734
#define SP_FEAT 0
#define SP_A    396
#define SP_B    (SP_A + 3 * 38 * 38 / 2)   // 396 + 2166 = 2562
#define SP_C    (SP_B + 3 * 36 * 36 / 2)   // 2562 + 1944 = 4506
#define SMEM_ULL (SP_C + 3 * 34 * 34 / 2)  // 6240
#define SMEM_BYTES (SMEM_ULL * 8)          // 49920

// ---------------- fused conv stack + attention ----------------
__global__ __launch_bounds__(NT, 4) void conv_att_kernel(
    const float* __restrict__ xMain, const float* __restrict__ xThumb,
    float* __restrict__ outAll, int Hm, int B, int tRowM) {
    extern __shared__ __align__(16) ull pool[];
    ull*   sPack = pool + SP_FEAT;
    float* bufA  = (float*)(pool + SP_A);
    float* bufB  = (float*)(pool + SP_B);
    float* bufC  = (float*)(pool + SP_C);

    int mainTotal = B * tRowM * tRowM;
    int bid = blockIdx.x;
    const float* src; float* dst;
    int H, tRow, b, tile;
    if (bid < mainTotal) {
        int per = tRowM * tRowM;
        b = bid / per; tile = bid - b * per;
        H = Hm; tRow = tRowM;
        src = xMain + (size_t)b * 3 * H * H;
        dst = outAll + (size_t)b * 3 * H * H;
    } else {
        int r = bid - mainTotal;
        b = r >> 2; tile = r & 3;
        H = 64; tRow = 2;
        src = xThumb + (size_t)b * 3 * 64 * 64;
        dst = outAll + (size_t)B * 3 * Hm * Hm + (size_t)b * 3 * 64 * 64;
    }
    int ty = tile / tRow, tx = tile - ty * tRow;
    int y0 = ty * TILE, x0 = tx * TILE;
    int tid = threadIdx.x;

    // splat features into reordered packed SMEM table
    const float* fb = g_feat + b * FEAT_DIM;
    for (int q = tid; q < 396; q += NT) {
        float f;
        if (q < 288) {                       // 3x conv3 layers, 96 slots each
            int layer = q / 96, r = q - layer * 96;
            if (r < 90) {
                int g = r / 10, j = r - g * 10;
                if (j < 9) {
                    int ic = g / 3, ky = g - ic * 3;
                    int kx = j / 3, oc = j - kx * 3;
                    f = fb[layer * 84 + oc * 27 + ic * 9 + ky * 3 + kx];
                } else f = 0.0f;             // pad
            } else if (r < 93) {
                f = fb[layer * 84 + 81 + (r - 90)];   // bias
            } else f = 0.0f;                 // pad
        } else if (q < 348) {
            f = fb[252 + (q - 288)];         // conv1x1 weights
        } else {
            f = fb[312 + (q - 348)];         // attention polys
        }
        sPack[q] = pack2(f, f);
    }

    // load input tile with halo 3 (zero-padded at borders)
    for (int i = tid; i < 3 * 38 * 38; i += NT) {
        int c = i / (38 * 38);
        int r = i - c * (38 * 38);
        int y = r / 38, xx = r - y * 38;
        int gy = y0 - 3 + y, gx = x0 - 3 + xx;
        float v = 0.0f;
        if (gy >= 0 && gy < H && gx >= 0 && gx < H)
            v = __ldg(&src[((size_t)c * H + gy) * H + gx]);
        bufA[i] = v;
    }
    __syncthreads();

    // L1: bufA(38) -> bufB(36)
    conv3_pairs<38, 36, 3, true>(bufA, bufB, sPack, tid, (ull(*)[3])nullptr);
    __syncthreads();

    // L2: bufB(36) -> bufC(34)   (bufA stays intact for the residual)
    conv3_pairs<36, 34, 3, true>(bufB, bufC, sPack + 96, tid, (ull(*)[3])nullptr);
    __syncthreads();

    // L3: bufC(34) -> registers (2 pair-slots/thread, exactly 32x32 tile)
    ull cur[2][3];
    conv3_pairs<34, 32, 2, false>(bufC, (float*)nullptr, sPack + 192, tid, cur);

    // 5x conv1x1 (packed, in registers)
    #pragma unroll
    for (int l = 0; l < 5; l++) {
        const ull* wl = sPack + 288 + l * 12;
        ull W0 = wl[0], W1 = wl[1], W2 = wl[2];
        ull W3 = wl[3], W4 = wl[4], W5 = wl[5];
        ull W6 = wl[6], W7 = wl[7], W8 = wl[8];
        ull B0 = wl[9], B1 = wl[10], B2 = wl[11];
        #pragma unroll
        for (int k = 0; k < 2; k++) {
            ull c0 = cur[k][0], c1 = cur[k][1], c2 = cur[k][2];
            ull n0 = fma2(W0, c0, fma2(W1, c1, fma2(W2, c2, B0)));
            ull n1 = fma2(W3, c0, fma2(W4, c1, fma2(W5, c2, B1)));
            ull n2 = fma2(W6, c0, fma2(W7, c1, fma2(W8, c2, B2)));
            cur[k][0] = lrelu2(n0);
            cur[k][1] = lrelu2(n1);
            cur[k][2] = lrelu2(n2);
        }
    }

    // residual add (bufA still holds the input tile) + attention + store
    float invH = 1.0f / (float)H;
    #pragma unroll
    for (int k = 0; k < 2; k++) {
        int p = tid + k * NT;
        int y = p >> 4, x = (p & 15) * 2;
        int gy = y0 + y, gx = x0 + x;
        float hv = (float)gy * invH;
        ull hP = pack2(hv, hv);
        ull wP = pack2((float)gx * invH, (float)(gx + 1) * invH);
        #pragma unroll
        for (int oc = 0; oc < 3; oc++) {
            const float* q = &bufA[(oc * 38 + 3 + y) * 38 + 3 + x];
            ull v = add2(pack2(q[0], q[1]), cur[k][oc]);
            ull att = (ull)ONE2;
            #pragma unroll
            for (int i = 0; i < 4; i++) {
                const ull* f = sPack + 348 + oc * 16 + i * 4;
                ull t = fma2(f[0], hP, fma2(f[1], wP, fma2(f[2], v, f[3])));
                att = mul2(att, t);
            }
            ull r = mul2(v, add2((ull)ONE2, att));
            *(ull*)&dst[((size_t)oc * H + gy) * H + gx] = r;
        }
    }
}

// ---------------- launch ----------------
extern "C" void kernel_launch(void* const* d_in, const int* in_sizes, int n_in,
                              void* d_out, int out_size) {
    const float* x     = (const float*)d_in[0];
    const float* thumb = (const float*)d_in[1];
    const float* Wm    = (const float*)d_in[2];
    const float* bm    = (const float*)d_in[3];
    float* out = (float*)d_out;

    int Ht = 64;
    int B  = in_sizes[1] / (3 * Ht * Ht);
    if (B < 1) B = 1;
    if (B > MAXB) B = MAXB;
    int hw = in_sizes[0] / (3 * B);
    int Hm = (int)(sqrt((double)hw) + 0.5);

    cudaFuncSetAttribute(conv_att_kernel,
                         cudaFuncAttributeMaxDynamicSharedMemorySize, SMEM_BYTES);

    feat_kernel<<<B, FT>>>(thumb, Wm, bm, Ht * Ht);

    int tRowM = Hm / TILE;
    int total = B * tRowM * tRowM + B * 4;
    conv_att_kernel<<<total, NT, SMEM_BYTES>>>(x, thumb, out, Hm, B, tRowM);
}

// round 7
// speedup vs baseline: 1.0185x; 1.0185x over previous
#include <cuda_runtime.h>
#include <math.h>

typedef unsigned long long ull;

#define FEAT_DIM 360
#define MAXB     32
#define NT       256
#define TILE     32

__device__ float g_feat[MAXB * FEAT_DIM];

// ---------------- packed f32x2 helpers ----------------
__device__ __forceinline__ ull pack2(float lo, float hi) {
    ull r; asm("mov.b64 %0, {%1, %2};" : "=l"(r) : "f"(lo), "f"(hi)); return r;
}
__device__ __forceinline__ ull fma2(ull a, ull b, ull c) {
    ull r; asm("fma.rn.f32x2 %0, %1, %2, %3;" : "=l"(r) : "l"(a), "l"(b), "l"(c)); return r;
}
__device__ __forceinline__ ull mul2(ull a, ull b) {
    ull r; asm("mul.rn.f32x2 %0, %1, %2;" : "=l"(r) : "l"(a), "l"(b)); return r;
}
__device__ __forceinline__ ull add2(ull a, ull b) {
    ull r; asm("add.rn.f32x2 %0, %1, %2;" : "=l"(r) : "l"(a), "l"(b)); return r;
}

#define C06P 0x3F19999A3F19999AULL   // (0.6f, 0.6f)
#define C04P 0x3ECCCCCD3ECCCCCDULL   // (0.4f, 0.4f)
#define ONE2 0x3F8000003F800000ULL   // (1.0f, 1.0f)

// lrelu(v) = 0.6*v + 0.4*|v|  (exact), branch-free packed
__device__ __forceinline__ ull lrelu2(ull v) {
    ull a = v & 0x7FFFFFFF7FFFFFFFULL;
    return fma2(a, (ull)C04P, mul2(v, (ull)C06P));
}

// ---------------- merged preamble: mean(thumb) + GEMV ----------------
#define FT 384
__global__ void feat_kernel(const float* __restrict__ thumb,
                            const float* __restrict__ Wm,
                            const float* __restrict__ bm, int HW) {
    int b = blockIdx.x;
    int tid = threadIdx.x;
    __shared__ float red[FT / 32][3];
    __shared__ float m[3];
    const float4* p = (const float4*)(thumb + (size_t)b * 3 * HW);
    int n4c = HW / 4;
    float s[3];
    #pragma unroll
    for (int c = 0; c < 3; c++) {
        float acc = 0.0f;
        for (int i = tid; i < n4c; i += FT) {
            float4 v = p[c * n4c + i];
            acc += (v.x + v.y) + (v.z + v.w);
        }
        s[c] = acc;
    }
    #pragma unroll
    for (int c = 0; c < 3; c++) {
        float v = s[c];
        #pragma unroll
        for (int o = 16; o > 0; o >>= 1) v += __shfl_down_sync(0xffffffffu, v, o);
        if ((tid & 31) == 0) red[tid >> 5][c] = v;
    }
    __syncthreads();
    if (tid == 0) {
        float inv = 1.0f / (float)HW;
        #pragma unroll
        for (int c = 0; c < 3; c++) {
            float t = 0.0f;
            #pragma unroll
            for (int w = 0; w < FT / 32; w++) t += red[w][c];
            m[c] = t * inv;
        }
    }
    __syncthreads();
    if (tid < FEAT_DIM) {
        g_feat[b * FEAT_DIM + tid] =
            m[0] * Wm[tid] + m[1] * Wm[FEAT_DIM + tid] + m[2] * Wm[2 * FEAT_DIM + tid]
            + bm[tid];
    }
}

// ---------------- one 3x3 conv layer on pixel pairs ----------------
// kx-major weight staging: per (ic,ky) the slot operands (v0,v1,v2) are loaded
// once and held; per kx only 3 packed weights are live. Peak liveness ~55 regs.
// wPack layout (R3): [oc*27 + ic*9 + ky*3 + kx], bias at 81..83.
template <int S, int D, int SLOTS, bool STORE>
__device__ __forceinline__ void conv3_pairs(const float* __restrict__ src,
                                            float* __restrict__ dst,
                                            const ull* __restrict__ wPack,
                                            int tid, ull outReg[][3]) {
    constexpr int PW = D / 2;
    constexpr int NP = D * PW;
    int off[SLOTS];
    #pragma unroll
    for (int k = 0; k < SLOTS; k++) {
        int p = tid + k * NT;
        int y = p / PW, x = (p - y * PW) * 2;
        off[k] = y * S + x;
    }
    ull acc[SLOTS][3];
    #pragma unroll
    for (int oc = 0; oc < 3; oc++) {
        ull bb = wPack[81 + oc];
        #pragma unroll
        for (int k = 0; k < SLOTS; k++) acc[k][oc] = bb;
    }
    #pragma unroll
    for (int ic = 0; ic < 3; ic++) {
        #pragma unroll
        for (int ky = 0; ky < 3; ky++) {
            // load operands for all slots once
            ull v0[SLOTS], v1[SLOTS], v2[SLOTS];
            #pragma unroll
            for (int k = 0; k < SLOTS; k++) {
                bool active = ((k + 1) * NT <= NP) || (tid + k * NT < NP);
                if (active) {
                    const float* s = src + ic * S * S + ky * S + off[k];
                    float2 a = *(const float2*)s;
                    float2 b = *(const float2*)(s + 2);
                    v0[k] = pack2(a.x, a.y);
                    v1[k] = pack2(a.y, b.x);
                    v2[k] = pack2(b.x, b.y);
                }
            }
            // kx = 0
            {
                ull wa = wPack[     ic * 9 + ky * 3 + 0];
                ull wb = wPack[27 + ic * 9 + ky * 3 + 0];
                ull wc = wPack[54 + ic * 9 + ky * 3 + 0];
                #pragma unroll
                for (int k = 0; k < SLOTS; k++) {
                    bool active = ((k + 1) * NT <= NP) || (tid + k * NT < NP);
                    if (active) {
                        acc[k][0] = fma2(wa, v0[k], acc[k][0]);
                        acc[k][1] = fma2(wb, v0[k], acc[k][1]);
                        acc[k][2] = fma2(wc, v0[k], acc[k][2]);
                    }
                }
            }
            // kx = 1
            {
                ull wa = wPack[     ic * 9 + ky * 3 + 1];
                ull wb = wPack[27 + ic * 9 + ky * 3 + 1];
                ull wc = wPack[54 + ic * 9 + ky * 3 + 1];
                #pragma unroll
                for (int k = 0; k < SLOTS; k++) {
                    bool active = ((k + 1) * NT <= NP) || (tid + k * NT < NP);
                    if (active) {
                        acc[k][0] = fma2(wa, v1[k], acc[k][0]);
                        acc[k][1] = fma2(wb, v1[k], acc[k][1]);
                        acc[k][2] = fma2(wc, v1[k], acc[k][2]);
                    }
                }
            }
            // kx = 2
            {
                ull wa = wPack[     ic * 9 + ky * 3 + 2];
                ull wb = wPack[27 + ic * 9 + ky * 3 + 2];
                ull wc = wPack[54 + ic * 9 + ky * 3 + 2];
                #pragma unroll
                for (int k = 0; k < SLOTS; k++) {
                    bool active = ((k + 1) * NT <= NP) || (tid + k * NT < NP);
                    if (active) {
                        acc[k][0] = fma2(wa, v2[k], acc[k][0]);
                        acc[k][1] = fma2(wb, v2[k], acc[k][1]);
                        acc[k][2] = fma2(wc, v2[k], acc[k][2]);
                    }
                }
            }
        }
    }
    #pragma unroll
    for (int k = 0; k < SLOTS; k++) {
        int p = tid + k * NT;
        bool active = ((k + 1) * NT <= NP) || (p < NP);
        if (active) {
            int y = p / PW, x = (p - y * PW) * 2;
            #pragma unroll
            for (int oc = 0; oc < 3; oc++) {
                ull r = lrelu2(acc[k][oc]);
                if (STORE) *(ull*)(dst + oc * D * D + y * D + x) = r;
                else       outReg[k][oc] = r;
            }
        }
    }
}

// smem partition (ull units): sPack 360 | bufA 2166 | bufB 1944 | bufC 1734
#define SP_FEAT 0
#define SP_A    360
#define SP_B    (SP_A + 3 * 38 * 38 / 2)
#define SP_C    (SP_B + 3 * 36 * 36 / 2)
#define SMEM_ULL (SP_C + 3 * 34 * 34 / 2)
#define SMEM_BYTES (SMEM_ULL * 8)        // 49,632 bytes

// ---------------- fused conv stack + attention ----------------
__global__ __launch_bounds__(NT, 4) void conv_att_kernel(
    const float* __restrict__ xMain, const float* __restrict__ xThumb,
    float* __restrict__ outAll, int Hm, int B, int tRowM) {
    extern __shared__ __align__(16) ull pool[];
    ull*   sPack = pool + SP_FEAT;
    float* bufA  = (float*)(pool + SP_A);
    float* bufB  = (float*)(pool + SP_B);
    float* bufC  = (float*)(pool + SP_C);

    int mainTotal = B * tRowM * tRowM;
    int bid = blockIdx.x;
    const float* src; float* dst;
    int H, tRow, b, tile;
    if (bid < mainTotal) {
        int per = tRowM * tRowM;
        b = bid / per; tile = bid - b * per;
        H = Hm; tRow = tRowM;
        src = xMain + (size_t)b * 3 * H * H;
        dst = outAll + (size_t)b * 3 * H * H;
    } else {
        int r = bid - mainTotal;
        b = r >> 2; tile = r & 3;
        H = 64; tRow = 2;
        src = xThumb + (size_t)b * 3 * 64 * 64;
        dst = outAll + (size_t)B * 3 * Hm * Hm + (size_t)b * 3 * 64 * 64;
    }
    int ty = tile / tRow, tx = tile - ty * tRow;
    int y0 = ty * TILE, x0 = tx * TILE;
    int tid = threadIdx.x;

    // load input tile with halo 3 (zero-padded) -- independent of g_feat,
    // overlaps the feat kernel under PDL.
    for (int i = tid; i < 3 * 38 * 38; i += NT) {
        int c = i / (38 * 38);
        int r = i - c * (38 * 38);
        int y = r / 38, xx = r - y * 38;
        int gy = y0 - 3 + y, gx = x0 - 3 + xx;
        float v = 0.0f;
        if (gy >= 0 && gy < H && gx >= 0 && gx < H)
            v = __ldg(&src[((size_t)c * H + gy) * H + gx]);
        bufA[i] = v;
    }

    // wait for feat_kernel's g_feat writes, then splat features
    cudaGridDependencySynchronize();
    for (int j = tid; j < FEAT_DIM; j += NT) {
        float f = g_feat[b * FEAT_DIM + j];
        sPack[j] = pack2(f, f);
    }
    __syncthreads();

    // L1: bufA(38) -> bufB(36)
    conv3_pairs<38, 36, 3, true>(bufA, bufB, sPack, tid, (ull(*)[3])nullptr);
    __syncthreads();

    // L2: bufB(36) -> bufC(34)   (bufA stays intact for the residual)
    conv3_pairs<36, 34, 3, true>(bufB, bufC, sPack + 84, tid, (ull(*)[3])nullptr);
    __syncthreads();

    // L3: bufC(34) -> registers (2 pair-slots/thread, exactly 32x32 tile)
    ull cur[2][3];
    conv3_pairs<34, 32, 2, false>(bufC, (float*)nullptr, sPack + 168, tid, cur);

    // 5x conv1x1 (packed, in registers)
    #pragma unroll
    for (int l = 0; l < 5; l++) {
        const ull* wl = sPack + 252 + l * 12;
        ull W0 = wl[0], W1 = wl[1], W2 = wl[2];
        ull W3 = wl[3], W4 = wl[4], W5 = wl[5];
        ull W6 = wl[6], W7 = wl[7], W8 = wl[8];
        ull B0 = wl[9], B1 = wl[10], B2 = wl[11];
        #pragma unroll
        for (int k = 0; k < 2; k++) {
            ull c0 = cur[k][0], c1 = cur[k][1], c2 = cur[k][2];
            ull n0 = fma2(W0, c0, fma2(W1, c1, fma2(W2, c2, B0)));
            ull n1 = fma2(W3, c0, fma2(W4, c1, fma2(W5, c2, B1)));
            ull n2 = fma2(W6, c0, fma2(W7, c1, fma2(W8, c2, B2)));
            cur[k][0] = lrelu2(n0);
            cur[k][1] = lrelu2(n1);
            cur[k][2] = lrelu2(n2);
        }
    }

    // residual add (bufA still intact) + polynomial attention + store
    float invH = 1.0f / (float)H;
    #pragma unroll
    for (int k = 0; k < 2; k++) {
        int p = tid + k * NT;
        int y = p >> 4, x = (p & 15) * 2;
        int gy = y0 + y, gx = x0 + x;
        float hv = (float)gy * invH;
        ull hP = pack2(hv, hv);
        ull wP = pack2((float)gx * invH, (float)(gx + 1) * invH);
        #pragma unroll
        for (int oc = 0; oc < 3; oc++) {
            const float* q = &bufA[(oc * 38 + 3 + y) * 38 + 3 + x];
            ull v = add2(pack2(q[0], q[1]), cur[k][oc]);
            ull att = (ull)ONE2;
            #pragma unroll
            for (int i = 0; i < 4; i++) {
                const ull* f = sPack + 312 + oc * 16 + i * 4;
                ull t = fma2(f[0], hP, fma2(f[1], wP, fma2(f[2], v, f[3])));
                att = mul2(att, t);
            }
            ull r = mul2(v, add2((ull)ONE2, att));
            *(ull*)&dst[((size_t)oc * H + gy) * H + gx] = r;
        }
    }
}

// ---------------- launch ----------------
extern "C" void kernel_launch(void* const* d_in, const int* in_sizes, int n_in,
                              void* d_out, int out_size) {
    const float* x     = (const float*)d_in[0];
    const float* thumb = (const float*)d_in[1];
    const float* Wm    = (const float*)d_in[2];
    const float* bm    = (const float*)d_in[3];
    float* out = (float*)d_out;

    int Ht = 64;
    int B  = in_sizes[1] / (3 * Ht * Ht);
    if (B < 1) B = 1;
    if (B > MAXB) B = MAXB;
    int hw = in_sizes[0] / (3 * B);
    int Hm = (int)(sqrt((double)hw) + 0.5);

    cudaFuncSetAttribute(conv_att_kernel,
                         cudaFuncAttributeMaxDynamicSharedMemorySize, SMEM_BYTES);

    feat_kernel<<<B, FT>>>(thumb, Wm, bm, Ht * Ht);

    int tRowM = Hm / TILE;
    int total = B * tRowM * tRowM + B * 4;

    // PDL launch: conv's tile loads overlap the feat kernel.
    cudaLaunchConfig_t cfg = {};
    cfg.gridDim = dim3(total);
    cfg.blockDim = dim3(NT);
    cfg.dynamicSmemBytes = SMEM_BYTES;
    cfg.stream = 0;
    cudaLaunchAttribute attrs[1];
    attrs[0].id = cudaLaunchAttributeProgrammaticStreamSerialization;
    attrs[0].val.programmaticStreamSerializationAllowed = 1;
    cfg.attrs = attrs;
    cfg.numAttrs = 1;
    cudaLaunchKernelEx(&cfg, conv_att_kernel, x, thumb, out, Hm, B, tRowM);
}

// round 8
// speedup vs baseline: 1.2091x; 1.1872x over previous
#include <cuda_runtime.h>
#include <math.h>

typedef unsigned long long ull;

#define FEAT_DIM 360
#define MAXB     32
#define NT       256
#define TILE     32

__device__ float g_feat[MAXB * FEAT_DIM];

// ---------------- packed f32x2 helpers ----------------
__device__ __forceinline__ ull pack2(float lo, float hi) {
    ull r; asm("mov.b64 %0, {%1, %2};" : "=l"(r) : "f"(lo), "f"(hi)); return r;
}
__device__ __forceinline__ ull fma2(ull a, ull b, ull c) {
    ull r; asm("fma.rn.f32x2 %0, %1, %2, %3;" : "=l"(r) : "l"(a), "l"(b), "l"(c)); return r;
}
__device__ __forceinline__ ull mul2(ull a, ull b) {
    ull r; asm("mul.rn.f32x2 %0, %1, %2;" : "=l"(r) : "l"(a), "l"(b)); return r;
}
__device__ __forceinline__ ull add2(ull a, ull b) {
    ull r; asm("add.rn.f32x2 %0, %1, %2;" : "=l"(r) : "l"(a), "l"(b)); return r;
}

#define C06P 0x3F19999A3F19999AULL   // (0.6f, 0.6f)
#define C04P 0x3ECCCCCD3ECCCCCDULL   // (0.4f, 0.4f)
#define ONE2 0x3F8000003F800000ULL   // (1.0f, 1.0f)

// lrelu(v) = 0.6*v + 0.4*|v|   (exact: v>=0 -> v, v<0 -> 0.2v), branch-free packed
__device__ __forceinline__ ull lrelu2(ull v) {
    ull a = v & 0x7FFFFFFF7FFFFFFFULL;
    return fma2(a, (ull)C04P, mul2(v, (ull)C06P));
}

// ---------------- merged preamble: mean(thumb) + GEMV, one launch ----------------
#define FT 384
__global__ void feat_kernel(const float* __restrict__ thumb,
                            const float* __restrict__ Wm,
                            const float* __restrict__ bm, int HW) {
    int b = blockIdx.x;
    int tid = threadIdx.x;
    __shared__ float red[FT / 32][3];
    __shared__ float m[3];
    const float4* p = (const float4*)(thumb + (size_t)b * 3 * HW);
    int n4c = HW / 4;
    float s[3];
    #pragma unroll
    for (int c = 0; c < 3; c++) {
        float acc = 0.0f;
        for (int i = tid; i < n4c; i += FT) {
            float4 v = p[c * n4c + i];
            acc += (v.x + v.y) + (v.z + v.w);
        }
        s[c] = acc;
    }
    #pragma unroll
    for (int c = 0; c < 3; c++) {
        float v = s[c];
        #pragma unroll
        for (int o = 16; o > 0; o >>= 1) v += __shfl_down_sync(0xffffffffu, v, o);
        if ((tid & 31) == 0) red[tid >> 5][c] = v;
    }
    __syncthreads();
    if (tid == 0) {
        float inv = 1.0f / (float)HW;
        #pragma unroll
        for (int c = 0; c < 3; c++) {
            float t = 0.0f;
            #pragma unroll
            for (int w = 0; w < FT / 32; w++) t += red[w][c];
            m[c] = t * inv;
        }
    }
    __syncthreads();
    if (tid < FEAT_DIM) {
        g_feat[b * FEAT_DIM + tid] =
            m[0] * Wm[tid] + m[1] * Wm[FEAT_DIM + tid] + m[2] * Wm[2 * FEAT_DIM + tid]
            + bm[tid];
    }
}

// ---------------- one 3x3 conv layer on pixel pairs (R3 body, proven best) ----------------
template <int S, int D, int SLOTS, bool STORE>
__device__ __forceinline__ void conv3_pairs(const float* __restrict__ src,
                                            float* __restrict__ dst,
                                            const ull* __restrict__ wPack,
                                            int tid, ull outReg[][3]) {
    constexpr int PW = D / 2;
    constexpr int NP = D * PW;
    int off[SLOTS];
    #pragma unroll
    for (int k = 0; k < SLOTS; k++) {
        int p = tid + k * NT;
        int y = p / PW, x = (p - y * PW) * 2;
        off[k] = y * S + x;
    }
    ull acc[SLOTS][3];
    #pragma unroll
    for (int oc = 0; oc < 3; oc++) {
        ull bb = wPack[81 + oc];
        #pragma unroll
        for (int k = 0; k < SLOTS; k++) acc[k][oc] = bb;
    }
    #pragma unroll
    for (int ic = 0; ic < 3; ic++) {
        #pragma unroll
        for (int ky = 0; ky < 3; ky++) {
            ull w00 = wPack[ 0 + ic * 9 + ky * 3 + 0];
            ull w01 = wPack[ 0 + ic * 9 + ky * 3 + 1];
            ull w02 = wPack[ 0 + ic * 9 + ky * 3 + 2];
            ull w10 = wPack[27 + ic * 9 + ky * 3 + 0];
            ull w11 = wPack[27 + ic * 9 + ky * 3 + 1];
            ull w12 = wPack[27 + ic * 9 + ky * 3 + 2];
            ull w20 = wPack[54 + ic * 9 + ky * 3 + 0];
            ull w21 = wPack[54 + ic * 9 + ky * 3 + 1];
            ull w22 = wPack[54 + ic * 9 + ky * 3 + 2];
            #pragma unroll
            for (int k = 0; k < SLOTS; k++) {
                bool active = ((k + 1) * NT <= NP) || (tid + k * NT < NP);
                if (active) {
                    const float* s = src + ic * S * S + ky * S + off[k];
                    float2 a = *(const float2*)s;
                    float2 b = *(const float2*)(s + 2);
                    ull v0 = pack2(a.x, a.y);
                    ull v1 = pack2(a.y, b.x);
                    ull v2 = pack2(b.x, b.y);
                    acc[k][0] = fma2(w00, v0, acc[k][0]);
                    acc[k][0] = fma2(w01, v1, acc[k][0]);
                    acc[k][0] = fma2(w02, v2, acc[k][0]);
                    acc[k][1] = fma2(w10, v0, acc[k][1]);
                    acc[k][1] = fma2(w11, v1, acc[k][1]);
                    acc[k][1] = fma2(w12, v2, acc[k][1]);
                    acc[k][2] = fma2(w20, v0, acc[k][2]);
                    acc[k][2] = fma2(w21, v1, acc[k][2]);
                    acc[k][2] = fma2(w22, v2, acc[k][2]);
                }
            }
        }
    }
    #pragma unroll
    for (int k = 0; k < SLOTS; k++) {
        int p = tid + k * NT;
        bool active = ((k + 1) * NT <= NP) || (p < NP);
        if (active) {
            int y = p / PW, x = (p - y * PW) * 2;
            #pragma unroll
            for (int oc = 0; oc < 3; oc++) {
                ull r = lrelu2(acc[k][oc]);
                if (STORE) *(ull*)(dst + oc * D * D + y * D + x) = r;
                else       outReg[k][oc] = r;
            }
        }
    }
}

// ---------------- fused conv stack + attention (main + thumb merged) ----------------
__global__ __launch_bounds__(NT, 3) void conv_att_kernel(
    const float* __restrict__ xMain, const float* __restrict__ xThumb,
    float* __restrict__ outAll, int Hm, int B, int tRowM) {
    __shared__ __align__(16) float bufA[3 * 38 * 38];
    __shared__ __align__(16) float bufB[3 * 36 * 36];
    __shared__ ull sPack[FEAT_DIM];

    int mainTotal = B * tRowM * tRowM;
    int bid = blockIdx.x;
    const float* src; float* dst;
    int H, tRow, b, tile;
    if (bid < mainTotal) {
        int per = tRowM * tRowM;
        b = bid / per; tile = bid - b * per;
        H = Hm; tRow = tRowM;
        src = xMain + (size_t)b * 3 * H * H;
        dst = outAll + (size_t)b * 3 * H * H;
    } else {
        int r = bid - mainTotal;
        b = r >> 2; tile = r & 3;
        H = 64; tRow = 2;
        src = xThumb + (size_t)b * 3 * 64 * 64;
        dst = outAll + (size_t)B * 3 * Hm * Hm + (size_t)b * 3 * 64 * 64;
    }
    int ty = tile / tRow, tx = tile - ty * tRow;
    int y0 = ty * TILE, x0 = tx * TILE;
    int tid = threadIdx.x;

    // load input tile with halo 3 (zero-padded at borders) -- independent of
    // g_feat, so under PDL this overlaps the feat kernel.
    for (int i = tid; i < 3 * 38 * 38; i += NT) {
        int c = i / (38 * 38);
        int r = i - c * (38 * 38);
        int y = r / 38, xx = r - y * 38;
        int gy = y0 - 3 + y, gx = x0 - 3 + xx;
        float v = 0.0f;
        if (gy >= 0 && gy < H && gx >= 0 && gx < H)
            v = __ldg(&src[((size_t)c * H + gy) * H + gx]);
        bufA[i] = v;
    }

    // wait for feat_kernel's g_feat writes, then splat features
    cudaGridDependencySynchronize();
    for (int j = tid; j < FEAT_DIM; j += NT) {
        float f = g_feat[b * FEAT_DIM + j];
        sPack[j] = pack2(f, f);
    }
    __syncthreads();

    // L1: bufA(38) -> bufB(36)
    conv3_pairs<38, 36, 3, true>(bufA, bufB, sPack, tid, (ull(*)[3])nullptr);

    // stash residual pairs (input tile center) before bufA is reused
    ull resP[2][3];
    #pragma unroll
    for (int k = 0; k < 2; k++) {
        int p = tid + k * NT;
        int y = p >> 4, x = (p & 15) * 2;
        #pragma unroll
        for (int oc = 0; oc < 3; oc++) {
            const float* q = &bufA[(oc * 38 + 3 + y) * 38 + 3 + x];
            resP[k][oc] = pack2(q[0], q[1]);
        }
    }
    __syncthreads();

    // L2: bufB(36) -> bufA(34)
    conv3_pairs<36, 34, 3, true>(bufB, bufA, sPack + 84, tid, (ull(*)[3])nullptr);
    __syncthreads();

    // L3: bufA(34) -> registers (2 pair-slots/thread, exactly 32x32 tile)
    ull cur[2][3];
    conv3_pairs<34, 32, 2, false>(bufA, (float*)nullptr, sPack + 168, tid, cur);

    // 5x conv1x1 (packed, in registers)
    #pragma unroll
    for (int l = 0; l < 5; l++) {
        const ull* wl = sPack + 252 + l * 12;
        ull W0 = wl[0], W1 = wl[1], W2 = wl[2];
        ull W3 = wl[3], W4 = wl[4], W5 = wl[5];
        ull W6 = wl[6], W7 = wl[7], W8 = wl[8];
        ull B0 = wl[9], B1 = wl[10], B2 = wl[11];
        #pragma unroll
        for (int k = 0; k < 2; k++) {
            ull c0 = cur[k][0], c1 = cur[k][1], c2 = cur[k][2];
            ull n0 = fma2(W0, c0, fma2(W1, c1, fma2(W2, c2, B0)));
            ull n1 = fma2(W3, c0, fma2(W4, c1, fma2(W5, c2, B1)));
            ull n2 = fma2(W6, c0, fma2(W7, c1, fma2(W8, c2, B2)));
            cur[k][0] = lrelu2(n0);
            cur[k][1] = lrelu2(n1);
            cur[k][2] = lrelu2(n2);
        }
    }
    // residual add
    #pragma unroll
    for (int k = 0; k < 2; k++)
        #pragma unroll
        for (int oc = 0; oc < 3; oc++)
            cur[k][oc] = add2(resP[k][oc], cur[k][oc]);

    // polynomial attention + store (packed, 2 pixels per store)
    float invH = 1.0f / (float)H;
    #pragma unroll
    for (int k = 0; k < 2; k++) {
        int p = tid + k * NT;
        int y = p >> 4, x = (p & 15) * 2;
        int gy = y0 + y, gx = x0 + x;
        float hv = (float)gy * invH;
        ull hP = pack2(hv, hv);
        ull wP = pack2((float)gx * invH, (float)(gx + 1) * invH);
        #pragma unroll
        for (int oc = 0; oc < 3; oc++) {
            ull v = cur[k][oc];
            ull att = (ull)ONE2;
            #pragma unroll
            for (int i = 0; i < 4; i++) {
                const ull* f = sPack + 312 + oc * 16 + i * 4;
                ull t = fma2(f[0], hP, fma2(f[1], wP, fma2(f[2], v, f[3])));
                att = mul2(att, t);
            }
            ull r = mul2(v, add2((ull)ONE2, att));
            *(ull*)&dst[((size_t)oc * H + gy) * H + gx] = r;
        }
    }
}

// ---------------- launch ----------------
extern "C" void kernel_launch(void* const* d_in, const int* in_sizes, int n_in,
                              void* d_out, int out_size) {
    const float* x     = (const float*)d_in[0];
    const float* thumb = (const float*)d_in[1];
    const float* Wm    = (const float*)d_in[2];
    const float* bm    = (const float*)d_in[3];
    float* out = (float*)d_out;

    int Ht = 64;
    int B  = in_sizes[1] / (3 * Ht * Ht);
    if (B < 1) B = 1;
    if (B > MAXB) B = MAXB;
    int hw = in_sizes[0] / (3 * B);
    int Hm = (int)(sqrt((double)hw) + 0.5);

    feat_kernel<<<B, FT>>>(thumb, Wm, bm, Ht * Ht);

    int tRowM = Hm / TILE;
    int total = B * tRowM * tRowM + B * 4;  // main tiles + thumb tiles

    // PDL launch: conv's tile loads overlap the feat kernel.
    cudaLaunchConfig_t cfg = {};
    cfg.gridDim = dim3(total);
    cfg.blockDim = dim3(NT);
    cfg.dynamicSmemBytes = 0;
    cfg.stream = 0;
    cudaLaunchAttribute attrs[1];
    attrs[0].id = cudaLaunchAttributeProgrammaticStreamSerialization;
    attrs[0].val.programmaticStreamSerializationAllowed = 1;
    cfg.attrs = attrs;
    cfg.numAttrs = 1;
    cudaLaunchKernelEx(&cfg, conv_att_kernel, x, thumb, out, Hm, B, tRowM);
}